// round 1
// baseline (speedup 1.0000x reference)
#include <cuda_runtime.h>
#include <cuda_bf16.h>

// Problem shape (fixed by dataset):
//   h: [N=200000, D=128] fp32
//   pos_src/pos_dst: [262144] int32
//   neg_src/neg_dst: [1048576] int32   (num_negs = 4)
//   out: [2] fp32  -> (loss, mrr)

#define DIM 128
#define E_POS_MAX 262144
#define E_NEG_MAX (262144 * 4)

// Scratch (allocation-free rule: __device__ globals)
__device__ float  g_pos_score[E_POS_MAX];
__device__ float  g_neg_score[E_NEG_MAX];
__device__ double g_loss_sum;
__device__ double g_mrr_sum;

__global__ void init_accum_kernel() {
    g_loss_sum = 0.0;
    g_mrr_sum  = 0.0;
}

// Warp-per-edge SDDMM + BCE loss accumulation.
// Lane i handles float4 element i of the 128-float rows (32 lanes * 4 floats).
__global__ __launch_bounds__(256) void score_loss_kernel(
    const float* __restrict__ h,
    const int*   __restrict__ pos_src,
    const int*   __restrict__ pos_dst,
    const int*   __restrict__ neg_src,
    const int*   __restrict__ neg_dst,
    int e_pos, int total_edges)
{
    const int warps_per_block = blockDim.x >> 5;
    const int warp_in_block   = threadIdx.x >> 5;
    const int lane            = threadIdx.x & 31;
    const long long e = (long long)blockIdx.x * warps_per_block + warp_in_block;

    __shared__ double wloss[8];

    double myloss = 0.0;
    if (e < total_edges) {
        const bool is_pos = (e < e_pos);
        int src, dst;
        if (is_pos) {
            src = pos_src[e];
            dst = pos_dst[e];
        } else {
            long long j = e - e_pos;
            src = neg_src[j];
            dst = neg_dst[j];
        }
        const float4* __restrict__ a =
            reinterpret_cast<const float4*>(h + (long long)src * DIM);
        const float4* __restrict__ b =
            reinterpret_cast<const float4*>(h + (long long)dst * DIM);
        float4 av = a[lane];
        float4 bv = b[lane];
        float d = av.x * bv.x + av.y * bv.y + av.z * bv.z + av.w * bv.w;

        #pragma unroll
        for (int off = 16; off; off >>= 1)
            d += __shfl_xor_sync(0xffffffffu, d, off);

        if (lane == 0) {
            const float s = d;
            // pos: softplus(s) - s = softplus(-s); neg: softplus(s).
            // Cancellation-free: log1p(exp(-|s|)) + max(t, 0), t = -s (pos) / s (neg)
            const float t    = is_pos ? -s : s;
            const float term = log1pf(expf(-fabsf(s))) + fmaxf(t, 0.0f);
            myloss = (double)term;
            if (is_pos) g_pos_score[e] = s;
            else        g_neg_score[e - e_pos] = s;
        }
    }

    if (lane == 0) wloss[warp_in_block] = myloss;
    __syncthreads();
    if (threadIdx.x == 0) {
        double s = 0.0;
        for (int i = 0; i < warps_per_block; i++) s += wloss[i];
        atomicAdd(&g_loss_sum, s);
    }
}

// Thread-per-positive-edge MRR.
// Stable descending argsort with positive at column 0 => rank = 1 + #{neg > pos}.
__global__ __launch_bounds__(256) void mrr_kernel(int e_pos) {
    const int i = blockIdx.x * blockDim.x + threadIdx.x;
    float v = 0.0f;
    if (i < e_pos) {
        const float p = g_pos_score[i];
        const float4 nb = reinterpret_cast<const float4*>(g_neg_score)[i];
        int rank = 1;
        rank += (nb.x > p);
        rank += (nb.y > p);
        rank += (nb.z > p);
        rank += (nb.w > p);
        v = 1.0f / (float)rank;
    }
    #pragma unroll
    for (int off = 16; off; off >>= 1)
        v += __shfl_xor_sync(0xffffffffu, v, off);

    __shared__ double ws[8];
    if ((threadIdx.x & 31) == 0) ws[threadIdx.x >> 5] = (double)v;
    __syncthreads();
    if (threadIdx.x == 0) {
        double s = 0.0;
        const int nw = blockDim.x >> 5;
        for (int k = 0; k < nw; k++) s += ws[k];
        atomicAdd(&g_mrr_sum, s);
    }
}

__global__ void finalize_kernel(float* __restrict__ out, int e_pos, int total_edges) {
    out[0] = (float)(g_loss_sum / (double)total_edges);
    out[1] = (float)(g_mrr_sum / (double)e_pos);
}

extern "C" void kernel_launch(void* const* d_in, const int* in_sizes, int n_in,
                              void* d_out, int out_size) {
    const float* h       = (const float*)d_in[0];
    const int*   pos_src = (const int*)d_in[1];
    const int*   pos_dst = (const int*)d_in[2];
    const int*   neg_src = (const int*)d_in[3];
    const int*   neg_dst = (const int*)d_in[4];

    const int e_pos = in_sizes[1];
    const int e_neg = in_sizes[3];
    const int total = e_pos + e_neg;

    float* out = (float*)d_out;

    init_accum_kernel<<<1, 1>>>();

    const int threads = 256;
    const int warps_per_block = threads / 32;
    const int blocks = (total + warps_per_block - 1) / warps_per_block;
    score_loss_kernel<<<blocks, threads>>>(h, pos_src, pos_dst,
                                           neg_src, neg_dst, e_pos, total);

    const int mrr_blocks = (e_pos + threads - 1) / threads;
    mrr_kernel<<<mrr_blocks, threads>>>(e_pos);

    finalize_kernel<<<1, 1>>>(out, e_pos, total);
}

// round 2
// speedup vs baseline: 2.1964x; 2.1964x over previous
#include <cuda_runtime.h>
#include <cuda_bf16.h>

// Problem shape (fixed by dataset):
//   h: [N=200000, D=128] fp32
//   pos_src/pos_dst: [262144] int32
//   neg_src/neg_dst: [1048576] int32   (num_negs = 4)
//   out: [2] fp32  -> (loss, mrr)

#define DIM 128
#define E_POS_MAX 262144
#define E_NEG_MAX (262144 * 4)

// Scratch (allocation-free rule: __device__ globals)
__device__ float  g_pos_score[E_POS_MAX];
__device__ float  g_neg_score[E_NEG_MAX];
__device__ double g_loss_sum;
__device__ double g_mrr_sum;

__global__ void init_accum_kernel() {
    g_loss_sum = 0.0;
    g_mrr_sum  = 0.0;
}

// Persistent grid-stride SDDMM + BCE loss.
// 8 threads per edge: thread sub-lane s loads float4 elements {s, s+8, s+16, s+24}
// of both rows -> 8 independent LDG.128 in flight per thread (MLP=8).
// 4 edges per warp. Loss accumulates per-thread; ONE atomicAdd per block.
__global__ __launch_bounds__(256) void score_loss_kernel(
    const float* __restrict__ h,
    const int*   __restrict__ pos_src,
    const int*   __restrict__ pos_dst,
    const int*   __restrict__ neg_src,
    const int*   __restrict__ neg_dst,
    int e_pos, int total_edges)
{
    const int sub  = threadIdx.x & 7;              // 0..7 within edge-group
    const int groups_per_block = blockDim.x >> 3;  // 32
    const long long gstride = (long long)gridDim.x * groups_per_block;
    long long e = (long long)blockIdx.x * groups_per_block + (threadIdx.x >> 3);

    double acc = 0.0;

    for (; e < total_edges; e += gstride) {
        const bool is_pos = (e < e_pos);
        long long j = is_pos ? e : (e - e_pos);
        int src = is_pos ? pos_src[j] : neg_src[j];
        int dst = is_pos ? pos_dst[j] : neg_dst[j];

        const float4* __restrict__ a =
            reinterpret_cast<const float4*>(h + (long long)src * DIM);
        const float4* __restrict__ b =
            reinterpret_cast<const float4*>(h + (long long)dst * DIM);

        // 8 independent loads -> deep MLP, then FMA chain
        float4 av0 = a[sub];      float4 bv0 = b[sub];
        float4 av1 = a[sub + 8];  float4 bv1 = b[sub + 8];
        float4 av2 = a[sub + 16]; float4 bv2 = b[sub + 16];
        float4 av3 = a[sub + 24]; float4 bv3 = b[sub + 24];

        float d = av0.x * bv0.x + av0.y * bv0.y + av0.z * bv0.z + av0.w * bv0.w;
        d += av1.x * bv1.x + av1.y * bv1.y + av1.z * bv1.z + av1.w * bv1.w;
        d += av2.x * bv2.x + av2.y * bv2.y + av2.z * bv2.z + av2.w * bv2.w;
        d += av3.x * bv3.x + av3.y * bv3.y + av3.z * bv3.z + av3.w * bv3.w;

        // reduce across the 8-lane group (xor of bits < 8 stays in-group)
        d += __shfl_xor_sync(0xffffffffu, d, 4);
        d += __shfl_xor_sync(0xffffffffu, d, 2);
        d += __shfl_xor_sync(0xffffffffu, d, 1);

        if (sub == 0) {
            const float s = d;
            // pos: softplus(s) - s = softplus(-s); neg: softplus(s).
            // Cancellation-free: log1p(exp(-|s|)) + max(t, 0)
            const float t    = is_pos ? -s : s;
            const float term = log1pf(expf(-fabsf(s))) + fmaxf(t, 0.0f);
            acc += (double)term;
            if (is_pos) g_pos_score[j] = s;
            else        g_neg_score[j] = s;
        }
    }

    // Block reduction: warp shuffle-reduce doubles, then shared, one atomic.
    #pragma unroll
    for (int off = 16; off; off >>= 1)
        acc += __shfl_xor_sync(0xffffffffu, acc, off);

    __shared__ double ws[8];
    if ((threadIdx.x & 31) == 0) ws[threadIdx.x >> 5] = acc;
    __syncthreads();
    if (threadIdx.x == 0) {
        double s = 0.0;
        const int nw = blockDim.x >> 5;
        for (int k = 0; k < nw; k++) s += ws[k];
        atomicAdd(&g_loss_sum, s);
    }
}

// Thread-per-positive-edge MRR.
// Stable descending argsort with positive at column 0 => rank = 1 + #{neg > pos}.
__global__ __launch_bounds__(256) void mrr_kernel(int e_pos) {
    const int i = blockIdx.x * blockDim.x + threadIdx.x;
    float v = 0.0f;
    if (i < e_pos) {
        const float p = g_pos_score[i];
        const float4 nb = reinterpret_cast<const float4*>(g_neg_score)[i];
        int rank = 1;
        rank += (nb.x > p);
        rank += (nb.y > p);
        rank += (nb.z > p);
        rank += (nb.w > p);
        v = 1.0f / (float)rank;
    }
    #pragma unroll
    for (int off = 16; off; off >>= 1)
        v += __shfl_xor_sync(0xffffffffu, v, off);

    __shared__ double ws[8];
    if ((threadIdx.x & 31) == 0) ws[threadIdx.x >> 5] = (double)v;
    __syncthreads();
    if (threadIdx.x == 0) {
        double s = 0.0;
        const int nw = blockDim.x >> 5;
        for (int k = 0; k < nw; k++) s += ws[k];
        atomicAdd(&g_mrr_sum, s);
    }
}

__global__ void finalize_kernel(float* __restrict__ out, int e_pos, int total_edges) {
    out[0] = (float)(g_loss_sum / (double)total_edges);
    out[1] = (float)(g_mrr_sum / (double)e_pos);
}

extern "C" void kernel_launch(void* const* d_in, const int* in_sizes, int n_in,
                              void* d_out, int out_size) {
    const float* h       = (const float*)d_in[0];
    const int*   pos_src = (const int*)d_in[1];
    const int*   pos_dst = (const int*)d_in[2];
    const int*   neg_src = (const int*)d_in[3];
    const int*   neg_dst = (const int*)d_in[4];

    const int e_pos = in_sizes[1];
    const int e_neg = in_sizes[3];
    const int total = e_pos + e_neg;

    float* out = (float*)d_out;

    init_accum_kernel<<<1, 1>>>();

    // Persistent: 8 blocks per SM on 148 SMs
    const int threads = 256;
    const int blocks = 148 * 8;
    score_loss_kernel<<<blocks, threads>>>(h, pos_src, pos_dst,
                                           neg_src, neg_dst, e_pos, total);

    const int mrr_blocks = (e_pos + threads - 1) / threads;
    mrr_kernel<<<mrr_blocks, threads>>>(e_pos);

    finalize_kernel<<<1, 1>>>(out, e_pos, total);
}

// round 3
// speedup vs baseline: 2.8998x; 1.3202x over previous
#include <cuda_runtime.h>
#include <cuda_fp16.h>
#include <cuda_bf16.h>

// Problem shape (fixed by dataset):
//   h: [N=200000, D=128] fp32
//   pos_src/pos_dst: [262144] int32
//   neg_src/neg_dst: [1048576] int32   (num_negs = 4)
//   out: [2] fp32  -> (loss, mrr)

#define DIM 128
#define N_NODES 200000
#define E_POS_MAX 262144
#define E_NEG_MAX (262144 * 4)

// Scratch (allocation-free rule: __device__ globals)
__device__ __half g_h_half[(size_t)N_NODES * DIM];   // 51.2 MB fp16 copy of h
__device__ float  g_pos_score[E_POS_MAX];
__device__ float  g_neg_score[E_NEG_MAX];
__device__ double g_loss_sum;
__device__ double g_mrr_sum;

__global__ void init_accum_kernel() {
    g_loss_sum = 0.0;
    g_mrr_sum  = 0.0;
}

// Streaming fp32 -> fp16 conversion of h. Each thread: 8 floats in, 8 halves out.
__global__ __launch_bounds__(256) void convert_kernel(
    const float* __restrict__ h, long long n_elems)
{
    const long long n8 = n_elems >> 3;
    const long long stride = (long long)gridDim.x * blockDim.x;
    for (long long i = (long long)blockIdx.x * blockDim.x + threadIdx.x;
         i < n8; i += stride) {
        const float4* src = reinterpret_cast<const float4*>(h) + i * 2;
        float4 f0 = src[0];
        float4 f1 = src[1];
        __half2 o[4];
        o[0] = __floats2half2_rn(f0.x, f0.y);
        o[1] = __floats2half2_rn(f0.z, f0.w);
        o[2] = __floats2half2_rn(f1.x, f1.y);
        o[3] = __floats2half2_rn(f1.z, f1.w);
        reinterpret_cast<float4*>(g_h_half)[i] = *reinterpret_cast<float4*>(o);
    }
}

// 8 fp16 elements (one float4-sized chunk) dotted in fp32.
__device__ __forceinline__ float dot8_h(float4 ra, float4 rb) {
    const __half2* pa = reinterpret_cast<const __half2*>(&ra);
    const __half2* pb = reinterpret_cast<const __half2*>(&rb);
    float d = 0.0f;
    #pragma unroll
    for (int k = 0; k < 4; k++) {
        float2 fa = __half22float2(pa[k]);
        float2 fb = __half22float2(pb[k]);
        d = fmaf(fa.x, fb.x, d);
        d = fmaf(fa.y, fb.y, d);
    }
    return d;
}

// Persistent grid-stride SDDMM + BCE loss on fp16 rows.
// 4 threads per edge: thread sub loads float4 chunks {sub, sub+4, sub+8, sub+12}
// of both 256B rows -> 8 independent LDG.128 per thread (MLP=8). 8 edges/warp.
__global__ __launch_bounds__(256) void score_loss_kernel(
    const int* __restrict__ pos_src,
    const int* __restrict__ pos_dst,
    const int* __restrict__ neg_src,
    const int* __restrict__ neg_dst,
    int e_pos, int total_edges)
{
    const int sub = threadIdx.x & 3;               // 0..3 within edge-group
    const int groups_per_block = blockDim.x >> 2;  // 64
    const long long gstride = (long long)gridDim.x * groups_per_block;
    long long e = (long long)blockIdx.x * groups_per_block + (threadIdx.x >> 2);

    double acc = 0.0;

    for (; e < total_edges; e += gstride) {
        const bool is_pos = (e < e_pos);
        long long j = is_pos ? e : (e - e_pos);
        int src = is_pos ? pos_src[j] : neg_src[j];
        int dst = is_pos ? pos_dst[j] : neg_dst[j];

        // fp16 row = 256 B = 16 float4 chunks
        const float4* __restrict__ a =
            reinterpret_cast<const float4*>(g_h_half + (size_t)src * DIM);
        const float4* __restrict__ b =
            reinterpret_cast<const float4*>(g_h_half + (size_t)dst * DIM);

        float4 av0 = a[sub];      float4 bv0 = b[sub];
        float4 av1 = a[sub + 4];  float4 bv1 = b[sub + 4];
        float4 av2 = a[sub + 8];  float4 bv2 = b[sub + 8];
        float4 av3 = a[sub + 12]; float4 bv3 = b[sub + 12];

        float d = dot8_h(av0, bv0);
        d += dot8_h(av1, bv1);
        d += dot8_h(av2, bv2);
        d += dot8_h(av3, bv3);

        // reduce across the 4-lane group
        d += __shfl_xor_sync(0xffffffffu, d, 2);
        d += __shfl_xor_sync(0xffffffffu, d, 1);

        if (sub == 0) {
            const float s = d;
            // pos: softplus(s) - s = softplus(-s); neg: softplus(s).
            // Cancellation-free: log1p(exp(-|s|)) + max(t, 0)
            const float t    = is_pos ? -s : s;
            const float term = log1pf(expf(-fabsf(s))) + fmaxf(t, 0.0f);
            acc += (double)term;
            if (is_pos) g_pos_score[j] = s;
            else        g_neg_score[j] = s;
        }
    }

    // Block reduction: warp shuffle-reduce doubles, then shared, one atomic.
    #pragma unroll
    for (int off = 16; off; off >>= 1)
        acc += __shfl_xor_sync(0xffffffffu, acc, off);

    __shared__ double ws[8];
    if ((threadIdx.x & 31) == 0) ws[threadIdx.x >> 5] = acc;
    __syncthreads();
    if (threadIdx.x == 0) {
        double s = 0.0;
        const int nw = blockDim.x >> 5;
        for (int k = 0; k < nw; k++) s += ws[k];
        atomicAdd(&g_loss_sum, s);
    }
}

// Thread-per-positive-edge MRR.
// Stable descending argsort with positive at column 0 => rank = 1 + #{neg > pos}.
__global__ __launch_bounds__(256) void mrr_kernel(int e_pos) {
    const int i = blockIdx.x * blockDim.x + threadIdx.x;
    float v = 0.0f;
    if (i < e_pos) {
        const float p = g_pos_score[i];
        const float4 nb = reinterpret_cast<const float4*>(g_neg_score)[i];
        int rank = 1;
        rank += (nb.x > p);
        rank += (nb.y > p);
        rank += (nb.z > p);
        rank += (nb.w > p);
        v = 1.0f / (float)rank;
    }
    #pragma unroll
    for (int off = 16; off; off >>= 1)
        v += __shfl_xor_sync(0xffffffffu, v, off);

    __shared__ double ws[8];
    if ((threadIdx.x & 31) == 0) ws[threadIdx.x >> 5] = (double)v;
    __syncthreads();
    if (threadIdx.x == 0) {
        double s = 0.0;
        const int nw = blockDim.x >> 5;
        for (int k = 0; k < nw; k++) s += ws[k];
        atomicAdd(&g_mrr_sum, s);
    }
}

__global__ void finalize_kernel(float* __restrict__ out, int e_pos, int total_edges) {
    out[0] = (float)(g_loss_sum / (double)total_edges);
    out[1] = (float)(g_mrr_sum / (double)e_pos);
}

extern "C" void kernel_launch(void* const* d_in, const int* in_sizes, int n_in,
                              void* d_out, int out_size) {
    const float* h       = (const float*)d_in[0];
    const int*   pos_src = (const int*)d_in[1];
    const int*   pos_dst = (const int*)d_in[2];
    const int*   neg_src = (const int*)d_in[3];
    const int*   neg_dst = (const int*)d_in[4];

    const long long n_h  = in_sizes[0];
    const int e_pos = in_sizes[1];
    const int e_neg = in_sizes[3];
    const int total = e_pos + e_neg;

    float* out = (float*)d_out;

    init_accum_kernel<<<1, 1>>>();

    const int threads = 256;
    const int pblocks = 148 * 8;

    convert_kernel<<<pblocks, threads>>>(h, n_h);

    score_loss_kernel<<<pblocks, threads>>>(pos_src, pos_dst,
                                            neg_src, neg_dst, e_pos, total);

    const int mrr_blocks = (e_pos + threads - 1) / threads;
    mrr_kernel<<<mrr_blocks, threads>>>(e_pos);

    finalize_kernel<<<1, 1>>>(out, e_pos, total);
}

// round 4
// speedup vs baseline: 3.1669x; 1.0921x over previous
#include <cuda_runtime.h>
#include <cuda_fp16.h>
#include <cuda_bf16.h>

// Problem shape (fixed by dataset):
//   h: [N=200000, D=128] fp32
//   pos_src/pos_dst: [262144] int32
//   neg_src/neg_dst: [1048576] int32   (num_negs = 4, contiguous per pos edge)
//   out: [2] fp32  -> (loss, mrr)

#define DIM 128
#define N_NODES 200000

// Scratch (allocation-free rule: __device__ globals)
__device__ __half  g_h_half[(size_t)N_NODES * DIM];   // 51.2 MB fp16 copy of h
__device__ double  g_loss_sum;
__device__ double  g_mrr_sum;
__device__ unsigned g_done;

// Streaming fp32 -> fp16 conversion of h; block 0 also resets accumulators.
__global__ __launch_bounds__(256) void convert_kernel(
    const float* __restrict__ h, long long n_elems)
{
    if (blockIdx.x == 0 && threadIdx.x == 0) {
        g_loss_sum = 0.0;
        g_mrr_sum  = 0.0;
        g_done     = 0u;
    }
    const long long n8 = n_elems >> 3;
    const long long stride = (long long)gridDim.x * blockDim.x;
    for (long long i = (long long)blockIdx.x * blockDim.x + threadIdx.x;
         i < n8; i += stride) {
        const float4* src = reinterpret_cast<const float4*>(h) + i * 2;
        float4 f0 = src[0];
        float4 f1 = src[1];
        __half2 o[4];
        o[0] = __floats2half2_rn(f0.x, f0.y);
        o[1] = __floats2half2_rn(f0.z, f0.w);
        o[2] = __floats2half2_rn(f1.x, f1.y);
        o[3] = __floats2half2_rn(f1.z, f1.w);
        reinterpret_cast<float4*>(g_h_half)[i] = *reinterpret_cast<float4*>(o);
    }
}

// 8 fp16 elements (one float4-sized chunk) dotted in fp32.
__device__ __forceinline__ float dot8_h(float4 ra, float4 rb) {
    const __half2* pa = reinterpret_cast<const __half2*>(&ra);
    const __half2* pb = reinterpret_cast<const __half2*>(&rb);
    float d = 0.0f;
    #pragma unroll
    for (int k = 0; k < 4; k++) {
        float2 fa = __half22float2(pa[k]);
        float2 fb = __half22float2(pb[k]);
        d = fmaf(fa.x, fb.x, d);
        d = fmaf(fa.y, fb.y, d);
    }
    return d;
}

// 4-thread-distributed dot of two fp16 rows (256 B each).
// Thread `sub` loads chunks {sub, sub+4, sub+8, sub+12} of both rows
// (8 independent LDG.128 -> MLP=8). Result broadcast to all 4 lanes.
__device__ __forceinline__ float edge_dot(int src, int dst, int sub) {
    const float4* __restrict__ a =
        reinterpret_cast<const float4*>(g_h_half + (size_t)src * DIM);
    const float4* __restrict__ b =
        reinterpret_cast<const float4*>(g_h_half + (size_t)dst * DIM);
    float4 av0 = a[sub];      float4 bv0 = b[sub];
    float4 av1 = a[sub + 4];  float4 bv1 = b[sub + 4];
    float4 av2 = a[sub + 8];  float4 bv2 = b[sub + 8];
    float4 av3 = a[sub + 12]; float4 bv3 = b[sub + 12];
    float d = dot8_h(av0, bv0);
    d += dot8_h(av1, bv1);
    d += dot8_h(av2, bv2);
    d += dot8_h(av3, bv3);
    d += __shfl_xor_sync(0xffffffffu, d, 2);
    d += __shfl_xor_sync(0xffffffffu, d, 1);
    return d;
}

__device__ __forceinline__ float softplus_neg_side(float s) {
    // softplus(s) for label 0
    return log1pf(expf(-fabsf(s))) + fmaxf(s, 0.0f);
}

// Fused SDDMM + BCE loss + MRR. One 4-thread group owns pos edge i and its
// 4 negatives (neg indices 4i..4i+3). All 5 scores stay in registers.
// Last finishing block writes the final outputs (no separate finalize kernel).
__global__ __launch_bounds__(256) void fused_kernel(
    const int* __restrict__ pos_src,
    const int* __restrict__ pos_dst,
    const int* __restrict__ neg_src,
    const int* __restrict__ neg_dst,
    float* __restrict__ out,
    int e_pos, int total_edges)
{
    const int sub = threadIdx.x & 3;               // 0..3 within edge-group
    const int groups_per_block = blockDim.x >> 2;  // 64
    const long long gstride = (long long)gridDim.x * groups_per_block;

    double lacc = 0.0;   // loss sum
    double macc = 0.0;   // mrr sum

    for (long long i = (long long)blockIdx.x * groups_per_block + (threadIdx.x >> 2);
         i < e_pos; i += gstride) {
        // Indices: pos pair + 4 contiguous neg pairs (vectorized int4)
        const int psrc = pos_src[i];
        const int pdst = pos_dst[i];
        const int4 ns = reinterpret_cast<const int4*>(neg_src)[i];
        const int4 nd = reinterpret_cast<const int4*>(neg_dst)[i];

        const float p  = edge_dot(psrc, pdst, sub);
        const float n0 = edge_dot(ns.x, nd.x, sub);
        const float n1 = edge_dot(ns.y, nd.y, sub);
        const float n2 = edge_dot(ns.z, nd.z, sub);
        const float n3 = edge_dot(ns.w, nd.w, sub);

        if (sub == 0) {
            // pos: softplus(p) - p = softplus(-p), cancellation-free form
            float loss5 = log1pf(expf(-fabsf(p))) + fmaxf(-p, 0.0f);
            loss5 += softplus_neg_side(n0);
            loss5 += softplus_neg_side(n1);
            loss5 += softplus_neg_side(n2);
            loss5 += softplus_neg_side(n3);
            lacc += (double)loss5;

            // Stable descending argsort, pos at col 0 => rank = 1 + #{neg > p}
            int rank = 1;
            rank += (n0 > p);
            rank += (n1 > p);
            rank += (n2 > p);
            rank += (n3 > p);
            macc += 1.0 / (double)rank;
        }
    }

    // Block reduction of both accumulators
    #pragma unroll
    for (int off = 16; off; off >>= 1) {
        lacc += __shfl_xor_sync(0xffffffffu, lacc, off);
        macc += __shfl_xor_sync(0xffffffffu, macc, off);
    }
    __shared__ double wl[8], wm[8];
    if ((threadIdx.x & 31) == 0) {
        wl[threadIdx.x >> 5] = lacc;
        wm[threadIdx.x >> 5] = macc;
    }
    __syncthreads();
    if (threadIdx.x == 0) {
        double sl = 0.0, sm = 0.0;
        const int nw = blockDim.x >> 5;
        for (int k = 0; k < nw; k++) { sl += wl[k]; sm += wm[k]; }
        atomicAdd(&g_loss_sum, sl);
        atomicAdd(&g_mrr_sum,  sm);
        __threadfence();
        unsigned t = atomicAdd(&g_done, 1u);
        if (t == gridDim.x - 1) {
            out[0] = (float)(g_loss_sum / (double)total_edges);
            out[1] = (float)(g_mrr_sum  / (double)e_pos);
        }
    }
}

extern "C" void kernel_launch(void* const* d_in, const int* in_sizes, int n_in,
                              void* d_out, int out_size) {
    const float* h       = (const float*)d_in[0];
    const int*   pos_src = (const int*)d_in[1];
    const int*   pos_dst = (const int*)d_in[2];
    const int*   neg_src = (const int*)d_in[3];
    const int*   neg_dst = (const int*)d_in[4];

    const long long n_h  = in_sizes[0];
    const int e_pos = in_sizes[1];
    const int e_neg = in_sizes[3];
    const int total = e_pos + e_neg;

    float* out = (float*)d_out;

    const int threads = 256;

    // Convert: persistent streaming pass
    convert_kernel<<<148 * 8, threads>>>(h, n_h);

    // Fused pass: 1024 blocks x 64 groups = 65536 group-slots.
    // E_POS = 2^18 -> exactly 4 iterations per slot (wave-exact, ~1% imbalance).
    fused_kernel<<<1024, threads>>>(pos_src, pos_dst, neg_src, neg_dst,
                                    out, e_pos, total);
}

// round 5
// speedup vs baseline: 3.2491x; 1.0259x over previous
#include <cuda_runtime.h>
#include <cuda_fp16.h>
#include <cuda_bf16.h>

// Problem shape (fixed by dataset):
//   h: [N=200000, D=128] fp32
//   pos_src/pos_dst: [262144] int32
//   neg_src/neg_dst: [1048576] int32   (num_negs = 4, contiguous per pos edge)
//   out: [2] fp32  -> (loss, mrr)

#define DIM 128
#define N_NODES 200000

// Scratch (allocation-free rule: __device__ globals)
__device__ __half   g_h_half[(size_t)N_NODES * DIM];   // 51.2 MB fp16 copy of h
__device__ double   g_loss_sum;
__device__ double   g_mrr_sum;
__device__ unsigned g_done;

// Streaming fp32 -> fp16 conversion of h; block 0 also resets accumulators.
__global__ __launch_bounds__(256) void convert_kernel(
    const float* __restrict__ h, long long n_elems)
{
    if (blockIdx.x == 0 && threadIdx.x == 0) {
        g_loss_sum = 0.0;
        g_mrr_sum  = 0.0;
        g_done     = 0u;
    }
    const long long n8 = n_elems >> 3;
    const long long stride = (long long)gridDim.x * blockDim.x;
    for (long long i = (long long)blockIdx.x * blockDim.x + threadIdx.x;
         i < n8; i += stride) {
        const float4* src = reinterpret_cast<const float4*>(h) + i * 2;
        float4 f0 = src[0];
        float4 f1 = src[1];
        __half2 o[4];
        o[0] = __floats2half2_rn(f0.x, f0.y);
        o[1] = __floats2half2_rn(f0.z, f0.w);
        o[2] = __floats2half2_rn(f1.x, f1.y);
        o[3] = __floats2half2_rn(f1.z, f1.w);
        reinterpret_cast<float4*>(g_h_half)[i] = *reinterpret_cast<float4*>(o);
    }
}

// 8 fp16 elements (one float4-sized chunk) dotted in fp32.
__device__ __forceinline__ float dot8_h(float4 ra, float4 rb) {
    const __half2* pa = reinterpret_cast<const __half2*>(&ra);
    const __half2* pb = reinterpret_cast<const __half2*>(&rb);
    float d = 0.0f;
    #pragma unroll
    for (int k = 0; k < 4; k++) {
        float2 fa = __half22float2(pa[k]);
        float2 fb = __half22float2(pb[k]);
        d = fmaf(fa.x, fb.x, d);
        d = fmaf(fa.y, fb.y, d);
    }
    return d;
}

// Per-thread partial dot for an 8-lane edge group. Lane `sub` (0..7) reads
// float4 chunks {sub, sub+8} of both 256B rows -> 8 consecutive lanes cover a
// full 128B line per LDG wavefront (minimum-wavefront gather). No shuffles here.
__device__ __forceinline__ float partial_dot(int src, int dst, int sub) {
    const float4* __restrict__ a =
        reinterpret_cast<const float4*>(g_h_half + (size_t)src * DIM);
    const float4* __restrict__ b =
        reinterpret_cast<const float4*>(g_h_half + (size_t)dst * DIM);
    float4 a0 = a[sub];     float4 b0 = b[sub];
    float4 a1 = a[sub + 8]; float4 b1 = b[sub + 8];
    return dot8_h(a0, b0) + dot8_h(a1, b1);
}

__device__ __forceinline__ float softplus_neg_side(float s) {
    // softplus(s) for label 0
    return log1pf(expf(-fabsf(s))) + fmaxf(s, 0.0f);
}

// Fused SDDMM + BCE loss + MRR. One 8-thread group owns pos edge i and its
// 4 negatives (neg indices 4i..4i+3). All 5 partial dots are computed with no
// intervening shuffles (loads pipeline across edges), then reduced together.
__global__ __launch_bounds__(128) void fused_kernel(
    const int* __restrict__ pos_src,
    const int* __restrict__ pos_dst,
    const int* __restrict__ neg_src,
    const int* __restrict__ neg_dst,
    float* __restrict__ out,
    int e_pos, int total_edges)
{
    const int sub = threadIdx.x & 7;               // 0..7 within edge-group
    const int groups_per_block = blockDim.x >> 3;  // 16
    const long long gstride = (long long)gridDim.x * groups_per_block;

    double lacc = 0.0;   // loss sum
    double macc = 0.0;   // mrr sum

    for (long long i = (long long)blockIdx.x * groups_per_block + (threadIdx.x >> 3);
         i < e_pos; i += gstride) {
        const int psrc = pos_src[i];
        const int pdst = pos_dst[i];
        const int4 ns = reinterpret_cast<const int4*>(neg_src)[i];
        const int4 nd = reinterpret_cast<const int4*>(neg_dst)[i];

        // 5 partial dots, no shuffles in between -> deep MLP across edges
        float t0 = partial_dot(psrc, pdst, sub);
        float t1 = partial_dot(ns.x, nd.x, sub);
        float t2 = partial_dot(ns.y, nd.y, sub);
        float t3 = partial_dot(ns.z, nd.z, sub);
        float t4 = partial_dot(ns.w, nd.w, sub);

        // Reduce all 5 across the 8-lane group (xor 4,2,1 stays in-group)
        #pragma unroll
        for (int off = 4; off; off >>= 1) {
            t0 += __shfl_xor_sync(0xffffffffu, t0, off);
            t1 += __shfl_xor_sync(0xffffffffu, t1, off);
            t2 += __shfl_xor_sync(0xffffffffu, t2, off);
            t3 += __shfl_xor_sync(0xffffffffu, t3, off);
            t4 += __shfl_xor_sync(0xffffffffu, t4, off);
        }

        if (sub == 0) {
            const float p = t0;
            // pos: softplus(p) - p = softplus(-p), cancellation-free form
            float loss5 = log1pf(expf(-fabsf(p))) + fmaxf(-p, 0.0f);
            loss5 += softplus_neg_side(t1);
            loss5 += softplus_neg_side(t2);
            loss5 += softplus_neg_side(t3);
            loss5 += softplus_neg_side(t4);
            lacc += (double)loss5;

            // Stable descending argsort, pos at col 0 => rank = 1 + #{neg > p}
            int rank = 1;
            rank += (t1 > p);
            rank += (t2 > p);
            rank += (t3 > p);
            rank += (t4 > p);
            macc += 1.0 / (double)rank;
        }
    }

    // Block reduction of both accumulators
    #pragma unroll
    for (int off = 16; off; off >>= 1) {
        lacc += __shfl_xor_sync(0xffffffffu, lacc, off);
        macc += __shfl_xor_sync(0xffffffffu, macc, off);
    }
    __shared__ double wl[4], wm[4];
    if ((threadIdx.x & 31) == 0) {
        wl[threadIdx.x >> 5] = lacc;
        wm[threadIdx.x >> 5] = macc;
    }
    __syncthreads();
    if (threadIdx.x == 0) {
        double sl = 0.0, sm = 0.0;
        const int nw = blockDim.x >> 5;
        for (int k = 0; k < nw; k++) { sl += wl[k]; sm += wm[k]; }
        atomicAdd(&g_loss_sum, sl);
        atomicAdd(&g_mrr_sum,  sm);
        __threadfence();
        unsigned t = atomicAdd(&g_done, 1u);
        if (t == gridDim.x - 1) {
            out[0] = (float)(g_loss_sum / (double)total_edges);
            out[1] = (float)(g_mrr_sum  / (double)e_pos);
        }
    }
}

extern "C" void kernel_launch(void* const* d_in, const int* in_sizes, int n_in,
                              void* d_out, int out_size) {
    const float* h       = (const float*)d_in[0];
    const int*   pos_src = (const int*)d_in[1];
    const int*   pos_dst = (const int*)d_in[2];
    const int*   neg_src = (const int*)d_in[3];
    const int*   neg_dst = (const int*)d_in[4];

    const long long n_h  = in_sizes[0];
    const int e_pos = in_sizes[1];
    const int e_neg = in_sizes[3];
    const int total = e_pos + e_neg;

    float* out = (float*)d_out;

    // Convert: persistent streaming pass
    convert_kernel<<<148 * 8, 256>>>(h, n_h);

    // Fused pass: 1184 blocks x 16 groups = 18944 group-slots, grid-stride
    // (~13.8 iters/slot, <=7% raggedness, single wave on 148 SMs).
    fused_kernel<<<148 * 8, 128>>>(pos_src, pos_dst, neg_src, neg_dst,
                                   out, e_pos, total);
}

// round 6
// speedup vs baseline: 3.5823x; 1.1026x over previous
#include <cuda_runtime.h>
#include <cuda_fp16.h>
#include <cuda_bf16.h>

// Problem shape (fixed by dataset):
//   h: [N=200000, D=128] fp32
//   pos_src/pos_dst: [262144] int32
//   neg_src/neg_dst: [1048576] int32   (num_negs = 4, contiguous per pos edge)
//   out: [2] fp32  -> (loss, mrr)

#define DIM 128
#define N_NODES 200000

// Scratch (allocation-free rule: __device__ globals)
__device__ __half   g_h_half[(size_t)N_NODES * DIM];   // 51.2 MB fp16 copy of h
__device__ double   g_loss_sum;
__device__ double   g_mrr_sum;
__device__ unsigned g_done;

// Streaming fp32 -> fp16 conversion of h; block 0 also resets accumulators.
__global__ __launch_bounds__(256) void convert_kernel(
    const float* __restrict__ h, long long n_elems)
{
    if (blockIdx.x == 0 && threadIdx.x == 0) {
        g_loss_sum = 0.0;
        g_mrr_sum  = 0.0;
        g_done     = 0u;
    }
    const long long n8 = n_elems >> 3;
    const long long stride = (long long)gridDim.x * blockDim.x;
    for (long long i = (long long)blockIdx.x * blockDim.x + threadIdx.x;
         i < n8; i += stride) {
        const float4* src = reinterpret_cast<const float4*>(h) + i * 2;
        float4 f0 = src[0];
        float4 f1 = src[1];
        __half2 o[4];
        o[0] = __floats2half2_rn(f0.x, f0.y);
        o[1] = __floats2half2_rn(f0.z, f0.w);
        o[2] = __floats2half2_rn(f1.x, f1.y);
        o[3] = __floats2half2_rn(f1.z, f1.w);
        reinterpret_cast<float4*>(g_h_half)[i] = *reinterpret_cast<float4*>(o);
    }
}

// 16-element partial dot with fp16 multiply + ONE pairwise fp16 accumulate,
// then fp32 finish. Halves the dequant instruction count vs all-fp32 FMA.
// a0/b0 = chunk k, a1/b1 = chunk k+8 (8 halves each).
__device__ __forceinline__ float dot16_pair(uint4 a0, uint4 b0,
                                            uint4 a1, uint4 b1) {
    const __half2* A0 = reinterpret_cast<const __half2*>(&a0);
    const __half2* B0 = reinterpret_cast<const __half2*>(&b0);
    const __half2* A1 = reinterpret_cast<const __half2*>(&a1);
    const __half2* B1 = reinterpret_cast<const __half2*>(&b1);
    float s = 0.0f;
    #pragma unroll
    for (int k = 0; k < 4; k++) {
        __half2 p = __hfma2(A1[k], B1[k], __hmul2(A0[k], B0[k]));
        float2 f = __half22float2(p);
        s += f.x;
        s += f.y;
    }
    return s;
}

// Per-thread partial dot for an 8-lane edge group. Lane `sub` (0..7) reads
// float4-sized chunks {sub, sub+8} of both 256B rows -> 8 consecutive lanes
// cover a full 128B line per LDG wavefront. No shuffles here.
__device__ __forceinline__ float partial_dot(int src, int dst, int sub) {
    const uint4* __restrict__ a =
        reinterpret_cast<const uint4*>(g_h_half + (size_t)src * DIM);
    const uint4* __restrict__ b =
        reinterpret_cast<const uint4*>(g_h_half + (size_t)dst * DIM);
    uint4 a0 = a[sub];     uint4 b0 = b[sub];
    uint4 a1 = a[sub + 8]; uint4 b1 = b[sub + 8];
    return dot16_pair(a0, b0, a1, b1);
}

__device__ __forceinline__ float softplus_neg_side(float s) {
    // softplus(s) for label 0
    return log1pf(expf(-fabsf(s))) + fmaxf(s, 0.0f);
}

// Fused SDDMM + BCE loss + MRR. One 8-thread group owns pos edge i and its
// 4 negatives (neg indices 4i..4i+3). All 5 partial dots are computed with no
// intervening shuffles (loads pipeline across edges), then reduced together.
__global__ __launch_bounds__(128) void fused_kernel(
    const int* __restrict__ pos_src,
    const int* __restrict__ pos_dst,
    const int* __restrict__ neg_src,
    const int* __restrict__ neg_dst,
    float* __restrict__ out,
    int e_pos, int total_edges)
{
    const int sub = threadIdx.x & 7;               // 0..7 within edge-group
    const int groups_per_block = blockDim.x >> 3;  // 16
    const long long gstride = (long long)gridDim.x * groups_per_block;

    double lacc = 0.0;   // loss sum
    double macc = 0.0;   // mrr sum

    for (long long i = (long long)blockIdx.x * groups_per_block + (threadIdx.x >> 3);
         i < e_pos; i += gstride) {
        const int psrc = pos_src[i];
        const int pdst = pos_dst[i];
        const int4 ns = reinterpret_cast<const int4*>(neg_src)[i];
        const int4 nd = reinterpret_cast<const int4*>(neg_dst)[i];

        // 5 partial dots, no shuffles in between -> deep MLP across edges
        float t0 = partial_dot(psrc, pdst, sub);
        float t1 = partial_dot(ns.x, nd.x, sub);
        float t2 = partial_dot(ns.y, nd.y, sub);
        float t3 = partial_dot(ns.z, nd.z, sub);
        float t4 = partial_dot(ns.w, nd.w, sub);

        // Reduce all 5 across the 8-lane group (xor 4,2,1 stays in-group)
        #pragma unroll
        for (int off = 4; off; off >>= 1) {
            t0 += __shfl_xor_sync(0xffffffffu, t0, off);
            t1 += __shfl_xor_sync(0xffffffffu, t1, off);
            t2 += __shfl_xor_sync(0xffffffffu, t2, off);
            t3 += __shfl_xor_sync(0xffffffffu, t3, off);
            t4 += __shfl_xor_sync(0xffffffffu, t4, off);
        }

        if (sub == 0) {
            const float p = t0;
            // pos: softplus(p) - p = softplus(-p), cancellation-free form
            float loss5 = log1pf(expf(-fabsf(p))) + fmaxf(-p, 0.0f);
            loss5 += softplus_neg_side(t1);
            loss5 += softplus_neg_side(t2);
            loss5 += softplus_neg_side(t3);
            loss5 += softplus_neg_side(t4);
            lacc += (double)loss5;

            // Stable descending argsort, pos at col 0 => rank = 1 + #{neg > p}
            int rank = 1;
            rank += (t1 > p);
            rank += (t2 > p);
            rank += (t3 > p);
            rank += (t4 > p);
            macc += 1.0 / (double)rank;
        }
    }

    // Block reduction of both accumulators
    #pragma unroll
    for (int off = 16; off; off >>= 1) {
        lacc += __shfl_xor_sync(0xffffffffu, lacc, off);
        macc += __shfl_xor_sync(0xffffffffu, macc, off);
    }
    __shared__ double wl[4], wm[4];
    if ((threadIdx.x & 31) == 0) {
        wl[threadIdx.x >> 5] = lacc;
        wm[threadIdx.x >> 5] = macc;
    }
    __syncthreads();
    if (threadIdx.x == 0) {
        double sl = 0.0, sm = 0.0;
        const int nw = blockDim.x >> 5;
        for (int k = 0; k < nw; k++) { sl += wl[k]; sm += wm[k]; }
        atomicAdd(&g_loss_sum, sl);
        atomicAdd(&g_mrr_sum,  sm);
        __threadfence();
        unsigned t = atomicAdd(&g_done, 1u);
        if (t == gridDim.x - 1) {
            out[0] = (float)(g_loss_sum / (double)total_edges);
            out[1] = (float)(g_mrr_sum  / (double)e_pos);
        }
    }
}

extern "C" void kernel_launch(void* const* d_in, const int* in_sizes, int n_in,
                              void* d_out, int out_size) {
    const float* h       = (const float*)d_in[0];
    const int*   pos_src = (const int*)d_in[1];
    const int*   pos_dst = (const int*)d_in[2];
    const int*   neg_src = (const int*)d_in[3];
    const int*   neg_dst = (const int*)d_in[4];

    const long long n_h  = in_sizes[0];
    const int e_pos = in_sizes[1];
    const int e_neg = in_sizes[3];
    const int total = e_pos + e_neg;

    float* out = (float*)d_out;

    // Convert: persistent streaming pass
    convert_kernel<<<148 * 8, 256>>>(h, n_h);

    // Fused pass: 1184 blocks x 16 groups = 18944 group-slots, grid-stride
    // (~13.8 iters/slot, <=7% raggedness, single wave on 148 SMs).
    fused_kernel<<<148 * 8, 128>>>(pos_src, pos_dst, neg_src, neg_dst,
                                   out, e_pos, total);
}

// round 7
// speedup vs baseline: 3.5838x; 1.0004x over previous
#include <cuda_runtime.h>
#include <cuda_fp16.h>
#include <cuda_bf16.h>

// Problem shape (fixed by dataset):
//   h: [N=200000, D=128] fp32
//   pos_src/pos_dst: [262144] int32
//   neg_src/neg_dst: [1048576] int32   (num_negs = 4, contiguous per pos edge)
//   out: [2] fp32  -> (loss, mrr)

#define DIM 128
#define N_NODES 200000

// Scratch (allocation-free rule: __device__ globals)
__device__ __half   g_h_half[(size_t)N_NODES * DIM];   // 51.2 MB fp16 copy of h
__device__ double   g_loss_sum;
__device__ double   g_mrr_sum;
__device__ unsigned g_done;

// Streaming fp32 -> fp16 conversion of h; block 0 also resets accumulators.
__global__ __launch_bounds__(256) void convert_kernel(
    const float* __restrict__ h, long long n_elems)
{
    if (blockIdx.x == 0 && threadIdx.x == 0) {
        g_loss_sum = 0.0;
        g_mrr_sum  = 0.0;
        g_done     = 0u;
    }
    const long long n8 = n_elems >> 3;
    const long long stride = (long long)gridDim.x * blockDim.x;
    for (long long i = (long long)blockIdx.x * blockDim.x + threadIdx.x;
         i < n8; i += stride) {
        const float4* src = reinterpret_cast<const float4*>(h) + i * 2;
        float4 f0 = src[0];
        float4 f1 = src[1];
        __half2 o[4];
        o[0] = __floats2half2_rn(f0.x, f0.y);
        o[1] = __floats2half2_rn(f0.z, f0.w);
        o[2] = __floats2half2_rn(f1.x, f1.y);
        o[3] = __floats2half2_rn(f1.z, f1.w);
        reinterpret_cast<float4*>(g_h_half)[i] = *reinterpret_cast<float4*>(o);
    }
}

// 16-element partial dot with fp16 multiply + ONE pairwise fp16 accumulate,
// then fp32 finish. a0/b0 = chunk k, a1/b1 = chunk k+8 (8 halves each).
__device__ __forceinline__ float dot16_pair(uint4 a0, uint4 b0,
                                            uint4 a1, uint4 b1) {
    const __half2* A0 = reinterpret_cast<const __half2*>(&a0);
    const __half2* B0 = reinterpret_cast<const __half2*>(&b0);
    const __half2* A1 = reinterpret_cast<const __half2*>(&a1);
    const __half2* B1 = reinterpret_cast<const __half2*>(&b1);
    float s = 0.0f;
    #pragma unroll
    for (int k = 0; k < 4; k++) {
        __half2 p = __hfma2(A1[k], B1[k], __hmul2(A0[k], B0[k]));
        float2 f = __half22float2(p);
        s += f.x;
        s += f.y;
    }
    return s;
}

// Per-thread partial dot for an 8-lane edge group. Lane `sub` (0..7) reads
// float4-sized chunks {sub, sub+8} of both 256B rows -> 8 consecutive lanes
// cover a full 128B line per LDG wavefront. No shuffles here.
__device__ __forceinline__ float partial_dot(int src, int dst, int sub) {
    const uint4* __restrict__ a =
        reinterpret_cast<const uint4*>(g_h_half + (size_t)src * DIM);
    const uint4* __restrict__ b =
        reinterpret_cast<const uint4*>(g_h_half + (size_t)dst * DIM);
    uint4 a0 = a[sub];     uint4 b0 = b[sub];
    uint4 a1 = a[sub + 8]; uint4 b1 = b[sub + 8];
    return dot16_pair(a0, b0, a1, b1);
}

__device__ __forceinline__ float softplus_neg_side(float s) {
    // softplus(s) for label 0
    return log1pf(expf(-fabsf(s))) + fmaxf(s, 0.0f);
}

// Fused SDDMM + BCE loss + MRR. One 8-thread group owns pos edge i and its
// 4 negatives (neg indices 4i..4i+3). Register-capped (<=42 regs) to lift
// occupancy to ~48 warps/SM; per-thread accumulators in float.
__global__ __launch_bounds__(128, 12) void fused_kernel(
    const int* __restrict__ pos_src,
    const int* __restrict__ pos_dst,
    const int* __restrict__ neg_src,
    const int* __restrict__ neg_dst,
    float* __restrict__ out,
    int e_pos, int total_edges)
{
    const int sub = threadIdx.x & 7;               // 0..7 within edge-group
    const int groups_per_block = blockDim.x >> 3;  // 16
    const int gstride = gridDim.x * groups_per_block;

    float lacc = 0.0f;   // loss partial sum (per-thread, small magnitude)
    float macc = 0.0f;   // mrr partial sum

    for (int i = blockIdx.x * groups_per_block + (threadIdx.x >> 3);
         i < e_pos; i += gstride) {
        const int psrc = pos_src[i];
        const int pdst = pos_dst[i];
        const int4 ns = reinterpret_cast<const int4*>(neg_src)[i];
        const int4 nd = reinterpret_cast<const int4*>(neg_dst)[i];

        // 5 partial dots, no shuffles in between -> loads pipeline freely
        float t0 = partial_dot(psrc, pdst, sub);
        float t1 = partial_dot(ns.x, nd.x, sub);
        float t2 = partial_dot(ns.y, nd.y, sub);
        float t3 = partial_dot(ns.z, nd.z, sub);
        float t4 = partial_dot(ns.w, nd.w, sub);

        // Reduce all 5 across the 8-lane group (xor 4,2,1 stays in-group)
        #pragma unroll
        for (int off = 4; off; off >>= 1) {
            t0 += __shfl_xor_sync(0xffffffffu, t0, off);
            t1 += __shfl_xor_sync(0xffffffffu, t1, off);
            t2 += __shfl_xor_sync(0xffffffffu, t2, off);
            t3 += __shfl_xor_sync(0xffffffffu, t3, off);
            t4 += __shfl_xor_sync(0xffffffffu, t4, off);
        }

        if (sub == 0) {
            const float p = t0;
            // pos: softplus(p) - p = softplus(-p), cancellation-free form
            float loss5 = log1pf(expf(-fabsf(p))) + fmaxf(-p, 0.0f);
            loss5 += softplus_neg_side(t1);
            loss5 += softplus_neg_side(t2);
            loss5 += softplus_neg_side(t3);
            loss5 += softplus_neg_side(t4);
            lacc += loss5;

            // Stable descending argsort, pos at col 0 => rank = 1 + #{neg > p}
            int rank = 1;
            rank += (t1 > p);
            rank += (t2 > p);
            rank += (t3 > p);
            rank += (t4 > p);
            macc += 1.0f / (float)rank;
        }
    }

    // Block reduction (promote to double here; only 1 value per thread)
    double dl = (double)lacc;
    double dm = (double)macc;
    #pragma unroll
    for (int off = 16; off; off >>= 1) {
        dl += __shfl_xor_sync(0xffffffffu, dl, off);
        dm += __shfl_xor_sync(0xffffffffu, dm, off);
    }
    __shared__ double wl[4], wm[4];
    if ((threadIdx.x & 31) == 0) {
        wl[threadIdx.x >> 5] = dl;
        wm[threadIdx.x >> 5] = dm;
    }
    __syncthreads();
    if (threadIdx.x == 0) {
        double sl = 0.0, sm = 0.0;
        const int nw = blockDim.x >> 5;
        for (int k = 0; k < nw; k++) { sl += wl[k]; sm += wm[k]; }
        atomicAdd(&g_loss_sum, sl);
        atomicAdd(&g_mrr_sum,  sm);
        __threadfence();
        unsigned t = atomicAdd(&g_done, 1u);
        if (t == gridDim.x - 1) {
            out[0] = (float)(g_loss_sum / (double)total_edges);
            out[1] = (float)(g_mrr_sum  / (double)e_pos);
        }
    }
}

extern "C" void kernel_launch(void* const* d_in, const int* in_sizes, int n_in,
                              void* d_out, int out_size) {
    const float* h       = (const float*)d_in[0];
    const int*   pos_src = (const int*)d_in[1];
    const int*   pos_dst = (const int*)d_in[2];
    const int*   neg_src = (const int*)d_in[3];
    const int*   neg_dst = (const int*)d_in[4];

    const long long n_h  = in_sizes[0];
    const int e_pos = in_sizes[1];
    const int e_neg = in_sizes[3];
    const int total = e_pos + e_neg;

    float* out = (float*)d_out;

    // Convert: persistent streaming pass (HBM-bound, ~20 us)
    convert_kernel<<<148 * 8, 256>>>(h, n_h);

    // Fused pass: 1184 blocks x 16 groups, grid-stride.
    fused_kernel<<<148 * 8, 128>>>(pos_src, pos_dst, neg_src, neg_dst,
                                   out, e_pos, total);
}

// round 8
// speedup vs baseline: 3.7655x; 1.0507x over previous
#include <cuda_runtime.h>
#include <cuda_fp16.h>
#include <cuda_bf16.h>

// Problem shape (fixed by dataset):
//   h: [N=200000, D=128] fp32
//   pos_src/pos_dst: [262144] int32
//   neg_src/neg_dst: [1048576] int32   (num_negs = 4, contiguous per pos edge)
//   out: [2] fp32  -> (loss, mrr)

#define DIM 128
#define N_NODES 200000

// Scratch (allocation-free rule: __device__ globals)
__device__ __half   g_h_half[(size_t)N_NODES * DIM];   // 51.2 MB fp16 copy of h
__device__ double   g_loss_sum;
__device__ double   g_mrr_sum;
__device__ unsigned g_done;

// Streaming fp32 -> fp16 conversion of h; block 0 also resets accumulators.
__global__ __launch_bounds__(256) void convert_kernel(
    const float* __restrict__ h, long long n_elems)
{
    if (blockIdx.x == 0 && threadIdx.x == 0) {
        g_loss_sum = 0.0;
        g_mrr_sum  = 0.0;
        g_done     = 0u;
    }
    const long long n8 = n_elems >> 3;
    const long long stride = (long long)gridDim.x * blockDim.x;
    for (long long i = (long long)blockIdx.x * blockDim.x + threadIdx.x;
         i < n8; i += stride) {
        const float4* src = reinterpret_cast<const float4*>(h) + i * 2;
        float4 f0 = src[0];
        float4 f1 = src[1];
        __half2 o[4];
        o[0] = __floats2half2_rn(f0.x, f0.y);
        o[1] = __floats2half2_rn(f0.z, f0.w);
        o[2] = __floats2half2_rn(f1.x, f1.y);
        o[3] = __floats2half2_rn(f1.z, f1.w);
        reinterpret_cast<float4*>(g_h_half)[i] = *reinterpret_cast<float4*>(o);
    }
}

// 16-element partial dot with fp16 multiply + ONE pairwise fp16 accumulate,
// then fp32 finish. a0/b0 = chunk k, a1/b1 = chunk k+8 (8 halves each).
__device__ __forceinline__ float dot16_pair(uint4 a0, uint4 b0,
                                            uint4 a1, uint4 b1) {
    const __half2* A0 = reinterpret_cast<const __half2*>(&a0);
    const __half2* B0 = reinterpret_cast<const __half2*>(&b0);
    const __half2* A1 = reinterpret_cast<const __half2*>(&a1);
    const __half2* B1 = reinterpret_cast<const __half2*>(&b1);
    float s = 0.0f;
    #pragma unroll
    for (int k = 0; k < 4; k++) {
        __half2 p = __hfma2(A1[k], B1[k], __hmul2(A0[k], B0[k]));
        float2 f = __half22float2(p);
        s += f.x;
        s += f.y;
    }
    return s;
}

// Per-thread partial dot for an 8-lane edge group. Lane `sub` (0..7) reads
// float4-sized chunks {sub, sub+8} of both 256B rows -> 8 consecutive lanes
// cover a full 128B line per LDG wavefront. No shuffles here.
__device__ __forceinline__ float partial_dot(int src, int dst, int sub) {
    const uint4* __restrict__ a =
        reinterpret_cast<const uint4*>(g_h_half + (size_t)src * DIM);
    const uint4* __restrict__ b =
        reinterpret_cast<const uint4*>(g_h_half + (size_t)dst * DIM);
    uint4 a0 = a[sub];     uint4 b0 = b[sub];
    uint4 a1 = a[sub + 8]; uint4 b1 = b[sub + 8];
    return dot16_pair(a0, b0, a1, b1);
}

__device__ __forceinline__ float softplus_neg_side(float s) {
    // softplus(s) for label 0
    return log1pf(expf(-fabsf(s))) + fmaxf(s, 0.0f);
}

// Fused SDDMM + BCE loss + MRR. One 8-thread group owns pos edge i and its
// 4 negatives (neg indices 4i..4i+3). 12 blocks/SM resident (40 regs/thread
// fits 1536 threads in the 64K register file) -> 48 warps/SM.
__global__ __launch_bounds__(128, 12) void fused_kernel(
    const int* __restrict__ pos_src,
    const int* __restrict__ pos_dst,
    const int* __restrict__ neg_src,
    const int* __restrict__ neg_dst,
    float* __restrict__ out,
    int e_pos, int total_edges)
{
    const int sub = threadIdx.x & 7;               // 0..7 within edge-group
    const int groups_per_block = blockDim.x >> 3;  // 16
    const int gstride = gridDim.x * groups_per_block;

    float lacc = 0.0f;   // loss partial sum (per-thread, small magnitude)
    float macc = 0.0f;   // mrr partial sum

    for (int i = blockIdx.x * groups_per_block + (threadIdx.x >> 3);
         i < e_pos; i += gstride) {
        const int psrc = pos_src[i];
        const int pdst = pos_dst[i];
        const int4 ns = reinterpret_cast<const int4*>(neg_src)[i];
        const int4 nd = reinterpret_cast<const int4*>(neg_dst)[i];

        // 5 partial dots, no shuffles in between -> loads pipeline freely
        float t0 = partial_dot(psrc, pdst, sub);
        float t1 = partial_dot(ns.x, nd.x, sub);
        float t2 = partial_dot(ns.y, nd.y, sub);
        float t3 = partial_dot(ns.z, nd.z, sub);
        float t4 = partial_dot(ns.w, nd.w, sub);

        // Reduce all 5 across the 8-lane group (xor 4,2,1 stays in-group)
        #pragma unroll
        for (int off = 4; off; off >>= 1) {
            t0 += __shfl_xor_sync(0xffffffffu, t0, off);
            t1 += __shfl_xor_sync(0xffffffffu, t1, off);
            t2 += __shfl_xor_sync(0xffffffffu, t2, off);
            t3 += __shfl_xor_sync(0xffffffffu, t3, off);
            t4 += __shfl_xor_sync(0xffffffffu, t4, off);
        }

        if (sub == 0) {
            const float p = t0;
            // pos: softplus(p) - p = softplus(-p), cancellation-free form
            float loss5 = log1pf(expf(-fabsf(p))) + fmaxf(-p, 0.0f);
            loss5 += softplus_neg_side(t1);
            loss5 += softplus_neg_side(t2);
            loss5 += softplus_neg_side(t3);
            loss5 += softplus_neg_side(t4);
            lacc += loss5;

            // Stable descending argsort, pos at col 0 => rank = 1 + #{neg > p}
            int rank = 1;
            rank += (t1 > p);
            rank += (t2 > p);
            rank += (t3 > p);
            rank += (t4 > p);
            macc += 1.0f / (float)rank;
        }
    }

    // Block reduction (promote to double here; only 1 value per thread)
    double dl = (double)lacc;
    double dm = (double)macc;
    #pragma unroll
    for (int off = 16; off; off >>= 1) {
        dl += __shfl_xor_sync(0xffffffffu, dl, off);
        dm += __shfl_xor_sync(0xffffffffu, dm, off);
    }
    __shared__ double wl[4], wm[4];
    if ((threadIdx.x & 31) == 0) {
        wl[threadIdx.x >> 5] = dl;
        wm[threadIdx.x >> 5] = dm;
    }
    __syncthreads();
    if (threadIdx.x == 0) {
        double sl = 0.0, sm = 0.0;
        const int nw = blockDim.x >> 5;
        for (int k = 0; k < nw; k++) { sl += wl[k]; sm += wm[k]; }
        atomicAdd(&g_loss_sum, sl);
        atomicAdd(&g_mrr_sum,  sm);
        __threadfence();
        unsigned t = atomicAdd(&g_done, 1u);
        if (t == gridDim.x - 1) {
            out[0] = (float)(g_loss_sum / (double)total_edges);
            out[1] = (float)(g_mrr_sum  / (double)e_pos);
        }
    }
}

extern "C" void kernel_launch(void* const* d_in, const int* in_sizes, int n_in,
                              void* d_out, int out_size) {
    const float* h       = (const float*)d_in[0];
    const int*   pos_src = (const int*)d_in[1];
    const int*   pos_dst = (const int*)d_in[2];
    const int*   neg_src = (const int*)d_in[3];
    const int*   neg_dst = (const int*)d_in[4];

    const long long n_h  = in_sizes[0];
    const int e_pos = in_sizes[1];
    const int e_neg = in_sizes[3];
    const int total = e_pos + e_neg;

    float* out = (float*)d_out;

    // Convert: persistent streaming pass (HBM-bound, ~19 us floor)
    convert_kernel<<<148 * 8, 256>>>(h, n_h);

    // Fused pass: 12 blocks/SM resident -> 48 warps/SM (was 8 -> 32).
    // 1776 blocks x 16 groups = 28416 slots, ~9.2 iters/slot grid-stride.
    fused_kernel<<<148 * 12, 128>>>(pos_src, pos_dst, neg_src, neg_dst,
                                    out, e_pos, total);
}

// round 9
// speedup vs baseline: 3.9991x; 1.0620x over previous
#include <cuda_runtime.h>
#include <cuda_fp16.h>
#include <cuda_bf16.h>

// Problem shape (fixed by dataset):
//   h: [N=200000, D=128] fp32
//   pos_src/pos_dst: [262144] int32
//   neg_src/neg_dst: [1048576] int32   (num_negs = 4, contiguous per pos edge)
//   out: [2] fp32  -> (loss, mrr)

#define DIM 128
#define N_NODES 200000

// Scratch (allocation-free rule: __device__ globals)
__device__ __half   g_h_half[(size_t)N_NODES * DIM];   // 51.2 MB fp16 copy of h
__device__ double   g_loss_sum;
__device__ double   g_mrr_sum;
__device__ unsigned g_done;

// Streaming fp32 -> fp16 conversion of h; block 0 also resets accumulators.
__global__ __launch_bounds__(256) void convert_kernel(
    const float* __restrict__ h, long long n_elems)
{
    if (blockIdx.x == 0 && threadIdx.x == 0) {
        g_loss_sum = 0.0;
        g_mrr_sum  = 0.0;
        g_done     = 0u;
    }
    const long long n8 = n_elems >> 3;
    const long long stride = (long long)gridDim.x * blockDim.x;
    for (long long i = (long long)blockIdx.x * blockDim.x + threadIdx.x;
         i < n8; i += stride) {
        const float4* src = reinterpret_cast<const float4*>(h) + i * 2;
        float4 f0 = src[0];
        float4 f1 = src[1];
        __half2 o[4];
        o[0] = __floats2half2_rn(f0.x, f0.y);
        o[1] = __floats2half2_rn(f0.z, f0.w);
        o[2] = __floats2half2_rn(f1.x, f1.y);
        o[3] = __floats2half2_rn(f1.z, f1.w);
        reinterpret_cast<float4*>(g_h_half)[i] = *reinterpret_cast<float4*>(o);
    }
}

// 16-element partial dot: two depth-4 HFMA2 chains + one HADD2, single
// fp32 conversion at the end. ~12 SASS ops per edge (was ~24).
__device__ __forceinline__ float dot16_chain(uint4 a0, uint4 b0,
                                             uint4 a1, uint4 b1) {
    const __half2* A0 = reinterpret_cast<const __half2*>(&a0);
    const __half2* B0 = reinterpret_cast<const __half2*>(&b0);
    const __half2* A1 = reinterpret_cast<const __half2*>(&a1);
    const __half2* B1 = reinterpret_cast<const __half2*>(&b1);
    __half2 acc0 = __hmul2(A0[0], B0[0]);
    __half2 acc1 = __hmul2(A1[0], B1[0]);
    #pragma unroll
    for (int k = 1; k < 4; k++) {
        acc0 = __hfma2(A0[k], B0[k], acc0);
        acc1 = __hfma2(A1[k], B1[k], acc1);
    }
    float2 f = __half22float2(__hadd2(acc0, acc1));
    return f.x + f.y;
}

// Per-thread partial dot for an 8-lane edge group. Lane `sub` (0..7) reads
// float4-sized chunks {sub, sub+8} of both 256B rows -> 8 consecutive lanes
// cover a full 128B line per LDG wavefront. No shuffles here.
__device__ __forceinline__ float partial_dot(int src, int dst, int sub) {
    const uint4* __restrict__ a =
        reinterpret_cast<const uint4*>(g_h_half + (size_t)src * DIM);
    const uint4* __restrict__ b =
        reinterpret_cast<const uint4*>(g_h_half + (size_t)dst * DIM);
    uint4 a0 = a[sub];     uint4 b0 = b[sub];
    uint4 a1 = a[sub + 8]; uint4 b1 = b[sub + 8];
    return dot16_chain(a0, b0, a1, b1);
}

__device__ __forceinline__ float softplus_neg_side(float s) {
    // softplus(s) for label 0
    return log1pf(expf(-fabsf(s))) + fmaxf(s, 0.0f);
}

// Fused SDDMM + BCE loss + MRR. One 8-thread group owns pos edge i and its
// 4 negatives (neg indices 4i..4i+3). 12 blocks/SM resident -> 48 warps/SM.
__global__ __launch_bounds__(128, 12) void fused_kernel(
    const int* __restrict__ pos_src,
    const int* __restrict__ pos_dst,
    const int* __restrict__ neg_src,
    const int* __restrict__ neg_dst,
    float* __restrict__ out,
    int e_pos, int total_edges)
{
    const int sub = threadIdx.x & 7;               // 0..7 within edge-group
    const int groups_per_block = blockDim.x >> 3;  // 16
    const int gstride = gridDim.x * groups_per_block;

    float lacc = 0.0f;   // loss partial sum (per-thread, small magnitude)
    float macc = 0.0f;   // mrr partial sum

    for (int i = blockIdx.x * groups_per_block + (threadIdx.x >> 3);
         i < e_pos; i += gstride) {
        const int psrc = pos_src[i];
        const int pdst = pos_dst[i];
        const int4 ns = reinterpret_cast<const int4*>(neg_src)[i];
        const int4 nd = reinterpret_cast<const int4*>(neg_dst)[i];

        // 5 partial dots, no shuffles in between -> loads pipeline freely
        float t0 = partial_dot(psrc, pdst, sub);
        float t1 = partial_dot(ns.x, nd.x, sub);
        float t2 = partial_dot(ns.y, nd.y, sub);
        float t3 = partial_dot(ns.z, nd.z, sub);
        float t4 = partial_dot(ns.w, nd.w, sub);

        // Reduce all 5 across the 8-lane group (xor 4,2,1 stays in-group)
        #pragma unroll
        for (int off = 4; off; off >>= 1) {
            t0 += __shfl_xor_sync(0xffffffffu, t0, off);
            t1 += __shfl_xor_sync(0xffffffffu, t1, off);
            t2 += __shfl_xor_sync(0xffffffffu, t2, off);
            t3 += __shfl_xor_sync(0xffffffffu, t3, off);
            t4 += __shfl_xor_sync(0xffffffffu, t4, off);
        }

        if (sub == 0) {
            const float p = t0;
            // pos: softplus(p) - p = softplus(-p), cancellation-free form
            float loss5 = log1pf(expf(-fabsf(p))) + fmaxf(-p, 0.0f);
            loss5 += softplus_neg_side(t1);
            loss5 += softplus_neg_side(t2);
            loss5 += softplus_neg_side(t3);
            loss5 += softplus_neg_side(t4);
            lacc += loss5;

            // Stable descending argsort, pos at col 0 => rank = 1 + #{neg > p}
            int rank = 1;
            rank += (t1 > p);
            rank += (t2 > p);
            rank += (t3 > p);
            rank += (t4 > p);
            macc += 1.0f / (float)rank;
        }
    }

    // Block reduction (promote to double here; only 1 value per thread)
    double dl = (double)lacc;
    double dm = (double)macc;
    #pragma unroll
    for (int off = 16; off; off >>= 1) {
        dl += __shfl_xor_sync(0xffffffffu, dl, off);
        dm += __shfl_xor_sync(0xffffffffu, dm, off);
    }
    __shared__ double wl[4], wm[4];
    if ((threadIdx.x & 31) == 0) {
        wl[threadIdx.x >> 5] = dl;
        wm[threadIdx.x >> 5] = dm;
    }
    __syncthreads();
    if (threadIdx.x == 0) {
        double sl = 0.0, sm = 0.0;
        const int nw = blockDim.x >> 5;
        for (int k = 0; k < nw; k++) { sl += wl[k]; sm += wm[k]; }
        atomicAdd(&g_loss_sum, sl);
        atomicAdd(&g_mrr_sum,  sm);
        __threadfence();
        unsigned t = atomicAdd(&g_done, 1u);
        if (t == gridDim.x - 1) {
            out[0] = (float)(g_loss_sum / (double)total_edges);
            out[1] = (float)(g_mrr_sum  / (double)e_pos);
        }
    }
}

extern "C" void kernel_launch(void* const* d_in, const int* in_sizes, int n_in,
                              void* d_out, int out_size) {
    const float* h       = (const float*)d_in[0];
    const int*   pos_src = (const int*)d_in[1];
    const int*   pos_dst = (const int*)d_in[2];
    const int*   neg_src = (const int*)d_in[3];
    const int*   neg_dst = (const int*)d_in[4];

    const long long n_h  = in_sizes[0];
    const int e_pos = in_sizes[1];
    const int e_neg = in_sizes[3];
    const int total = e_pos + e_neg;

    float* out = (float*)d_out;

    // Convert: persistent streaming pass (HBM-bound, ~19 us floor)
    convert_kernel<<<148 * 8, 256>>>(h, n_h);

    // Fused pass: 12 blocks/SM resident -> 48 warps/SM.
    fused_kernel<<<148 * 12, 128>>>(pos_src, pos_dst, neg_src, neg_dst,
                                    out, e_pos, total);
}